// round 1
// baseline (speedup 1.0000x reference)
#include <cuda_runtime.h>
#include <cstdint>

// SOM forward: x[128,256] f32, weights[64,64,256] f32
// out = [ bmus(128*2 floats) , diffs(128*64*64*256 floats) ]
//
// HBM-write-bound: 512 MiB of diffs. Distances computed for free by
// accumulating sum((x-w)^2) while streaming diffs out; per-batch argmin
// via packed (d2_bits, m) atomicMin into a __device__ scratch array.

#define B 128
#define D 256
#define MAPM 4096          // 64*64 neurons
#define NPAIRS (B * MAPM)  // 524288 warps total

__device__ unsigned long long g_best[B];

__global__ void som_init_kernel() {
    if (threadIdx.x < B) g_best[threadIdx.x] = 0xFFFFFFFFFFFFFFFFULL;
}

__global__ __launch_bounds__(256) void som_main_kernel(
    const float* __restrict__ x,
    const float* __restrict__ w,
    float* __restrict__ diffs)
{
    const int gwarp = (blockIdx.x * 256 + threadIdx.x) >> 5; // 0..NPAIRS-1
    const int lane  = threadIdx.x & 31;
    const int b = gwarp >> 12;     // / 4096
    const int m = gwarp & 4095;    // % 4096

    const float4* __restrict__ xv = reinterpret_cast<const float4*>(x + (size_t)b * D);
    const float4* __restrict__ wv = reinterpret_cast<const float4*>(w + (size_t)m * D);
    float4* __restrict__ ov = reinterpret_cast<float4*>(diffs + ((size_t)b * MAPM + m) * D);

    float acc = 0.0f;
#pragma unroll
    for (int i = 0; i < 2; i++) {
        const int idx = lane * 2 + i;     // 0..63 float4s, 1KB contiguous per warp
        float4 xa = xv[idx];
        float4 wa = wv[idx];
        float4 dd;
        dd.x = xa.x - wa.x;
        dd.y = xa.y - wa.y;
        dd.z = xa.z - wa.z;
        dd.w = xa.w - wa.w;
        ov[idx] = dd;
        acc = fmaf(dd.x, dd.x, acc);
        acc = fmaf(dd.y, dd.y, acc);
        acc = fmaf(dd.z, dd.z, acc);
        acc = fmaf(dd.w, dd.w, acc);
    }

    // warp-reduce squared distance
#pragma unroll
    for (int off = 16; off; off >>= 1)
        acc += __shfl_down_sync(0xffffffffu, acc, off);

    if (lane == 0) {
        // acc >= 0 -> IEEE bits are monotone as unsigned. Low 32 bits carry m,
        // so ties resolve to the lowest index, matching argmin semantics.
        unsigned long long key =
            ((unsigned long long)__float_as_uint(acc) << 32) | (unsigned int)m;
        atomicMin(&g_best[b], key);
    }
}

__global__ void som_bmus_kernel(float* __restrict__ out_bmus) {
    const int b = threadIdx.x;
    if (b < B) {
        const unsigned int m = (unsigned int)(g_best[b] & 0xFFFFFFFFu);
        out_bmus[b * 2 + 0] = (float)(m >> 6);   // row = m / 64
        out_bmus[b * 2 + 1] = (float)(m & 63);   // col = m % 64
    }
}

extern "C" void kernel_launch(void* const* d_in, const int* in_sizes, int n_in,
                              void* d_out, int out_size) {
    const float* x = (const float*)d_in[0];
    const float* w = (const float*)d_in[1];
    float* out = (float*)d_out;

    float* bmus  = out;        // first 256 floats
    float* diffs = out + B * 2;

    som_init_kernel<<<1, 128>>>();
    som_main_kernel<<<NPAIRS / 8, 256>>>(x, w, diffs);
    som_bmus_kernel<<<1, 128>>>(bmus);
}

// round 2
// speedup vs baseline: 1.3696x; 1.3696x over previous
#include <cuda_runtime.h>
#include <cstdint>

// SOM forward: x[128,256] f32, weights[64,64,256] f32
// out = [ bmus(128*2 floats) , diffs(128*64*64*256 floats) ]
//
// Design: 1 warp per neuron m (4096 warps). w row cached in registers,
// x rows L1-resident, pure coalesced streaming-store of diffs.
// d2 accumulated in-flight; per-(b,m) argmin via packed u64 atomicMin.

#define B 128
#define D 256
#define MAPM 4096  // 64*64 neurons

__device__ unsigned long long g_best[B];

__global__ void som_init_kernel() {
    if (threadIdx.x < B) g_best[threadIdx.x] = 0xFFFFFFFFFFFFFFFFULL;
}

__global__ __launch_bounds__(256) void som_main_kernel(
    const float* __restrict__ x,
    const float* __restrict__ w,
    float* __restrict__ diffs)
{
    const int gwarp = (blockIdx.x * 256 + threadIdx.x) >> 5; // 0..4095 == m
    const int lane  = threadIdx.x & 31;
    const int m = gwarp;

    // Load this neuron's weight row into registers (2 float4 per lane,
    // contiguous 512B per instruction).
    const float4* __restrict__ wv = reinterpret_cast<const float4*>(w + (size_t)m * D);
    const float4 wa0 = wv[lane];
    const float4 wa1 = wv[32 + lane];

    const unsigned int mbits = (unsigned int)m;

#pragma unroll 4
    for (int b = 0; b < B; b++) {
        const float4* __restrict__ xv =
            reinterpret_cast<const float4*>(x + (size_t)b * D);
        float4 xa0 = xv[lane];
        float4 xa1 = xv[32 + lane];

        float4 d0, d1;
        d0.x = xa0.x - wa0.x;  d0.y = xa0.y - wa0.y;
        d0.z = xa0.z - wa0.z;  d0.w = xa0.w - wa0.w;
        d1.x = xa1.x - wa1.x;  d1.y = xa1.y - wa1.y;
        d1.z = xa1.z - wa1.z;  d1.w = xa1.w - wa1.w;

        float4* __restrict__ ov =
            reinterpret_cast<float4*>(diffs + ((size_t)b * MAPM + m) * D);
        __stcs(ov + lane,      d0);   // streaming store: evict-first in L2
        __stcs(ov + 32 + lane, d1);

        float acc;
        acc = d0.x * d0.x;
        acc = fmaf(d0.y, d0.y, acc);
        acc = fmaf(d0.z, d0.z, acc);
        acc = fmaf(d0.w, d0.w, acc);
        acc = fmaf(d1.x, d1.x, acc);
        acc = fmaf(d1.y, d1.y, acc);
        acc = fmaf(d1.z, d1.z, acc);
        acc = fmaf(d1.w, d1.w, acc);

#pragma unroll
        for (int off = 16; off; off >>= 1)
            acc += __shfl_down_sync(0xffffffffu, acc, off);

        if (lane == 0) {
            // acc >= 0 -> IEEE bits monotone as unsigned; low bits carry m so
            // ties resolve to lowest index (argmin semantics).
            unsigned long long key =
                ((unsigned long long)__float_as_uint(acc) << 32) | mbits;
            atomicMin(&g_best[b], key);
        }
    }
}

__global__ void som_bmus_kernel(float* __restrict__ out_bmus) {
    const int b = threadIdx.x;
    if (b < B) {
        const unsigned int m = (unsigned int)(g_best[b] & 0xFFFFFFFFu);
        out_bmus[b * 2 + 0] = (float)(m >> 6);   // row = m / 64
        out_bmus[b * 2 + 1] = (float)(m & 63);   // col = m % 64
    }
}

extern "C" void kernel_launch(void* const* d_in, const int* in_sizes, int n_in,
                              void* d_out, int out_size) {
    const float* x = (const float*)d_in[0];
    const float* w = (const float*)d_in[1];
    float* out = (float*)d_out;

    float* bmus  = out;        // first 256 floats
    float* diffs = out + B * 2;

    som_init_kernel<<<1, 128>>>();
    som_main_kernel<<<MAPM / 8, 256>>>(x, w, diffs);  // 512 blocks x 8 warps
    som_bmus_kernel<<<1, 128>>>(bmus);
}

// round 3
// speedup vs baseline: 1.6724x; 1.2211x over previous
#include <cuda_runtime.h>
#include <cstdint>

// SOM forward: x[128,256] f32, weights[64,64,256] f32
// out = [ bmus(128*2 floats) , diffs(128*64*64*256 floats) ]
//
// Single fused kernel: warp = (neuron m, 16-batch chunk). w row in registers,
// x L1-resident, coalesced streaming stores of diffs. d2 per (b,m) reduced in
// batches of 4 independent shuffle chains; argmin via atomicMax of ~packed key
// (zero-init friendly). Last block writes bmus and re-arms globals so the
// launch is graph-replay deterministic with ZERO setup kernels.

#define B 128
#define D 256
#define MAPM 4096            // 64*64 neurons
#define CHUNK 16             // batches per warp
#define NCHUNK (B / CHUNK)   // 8
#define WARPS_PER_BLOCK 8
#define NBLOCKS (MAPM * NCHUNK / WARPS_PER_BLOCK)  // 4096

__device__ unsigned long long g_best[B];   // zero-init; holds ~min_key
__device__ unsigned int g_done;            // zero-init ticket

__global__ __launch_bounds__(256) void som_fused_kernel(
    const float* __restrict__ x,
    const float* __restrict__ w,
    float* __restrict__ out)   // out = [bmus | diffs]
{
    float* __restrict__ diffs = out + B * 2;

    const int gwarp = (blockIdx.x * WARPS_PER_BLOCK) + (threadIdx.x >> 5);
    const int lane  = threadIdx.x & 31;
    const int m     = gwarp >> 3;          // 0..4095
    const int b0    = (gwarp & 7) * CHUNK; // chunk start batch

    // weight row in registers (contiguous 512B per LDG.128)
    const float4* __restrict__ wv = reinterpret_cast<const float4*>(w + (size_t)m * D);
    const float4 wa0 = wv[lane];
    const float4 wa1 = wv[32 + lane];

    const unsigned int mbits = (unsigned int)m;

#pragma unroll
    for (int g = 0; g < CHUNK / 4; g++) {
        float acc[4];
#pragma unroll
        for (int i = 0; i < 4; i++) {
            const int b = b0 + g * 4 + i;
            const float4* __restrict__ xv =
                reinterpret_cast<const float4*>(x + (size_t)b * D);
            float4 xa0 = xv[lane];
            float4 xa1 = xv[32 + lane];

            float4 d0, d1;
            d0.x = xa0.x - wa0.x;  d0.y = xa0.y - wa0.y;
            d0.z = xa0.z - wa0.z;  d0.w = xa0.w - wa0.w;
            d1.x = xa1.x - wa1.x;  d1.y = xa1.y - wa1.y;
            d1.z = xa1.z - wa1.z;  d1.w = xa1.w - wa1.w;

            float4* __restrict__ ov =
                reinterpret_cast<float4*>(diffs + ((size_t)b * MAPM + m) * D);
            __stcs(ov + lane,      d0);
            __stcs(ov + 32 + lane, d1);

            float a;
            a = d0.x * d0.x;
            a = fmaf(d0.y, d0.y, a);
            a = fmaf(d0.z, d0.z, a);
            a = fmaf(d0.w, d0.w, a);
            a = fmaf(d1.x, d1.x, a);
            a = fmaf(d1.y, d1.y, a);
            a = fmaf(d1.z, d1.z, a);
            a = fmaf(d1.w, d1.w, a);
            acc[i] = a;
        }

        // 4 independent warp reductions — chains interleave, no single
        // blocking dependency per store iteration.
#pragma unroll
        for (int off = 16; off; off >>= 1) {
#pragma unroll
            for (int i = 0; i < 4; i++)
                acc[i] += __shfl_down_sync(0xffffffffu, acc[i], off);
        }

        if (lane == 0) {
#pragma unroll
            for (int i = 0; i < 4; i++) {
                // min over key == max over ~key; zero-init works since all
                // ~key values are > 0. Low bits carry m -> lowest-index tie.
                unsigned long long key =
                    ((unsigned long long)__float_as_uint(acc[i]) << 32) | mbits;
                atomicMax(&g_best[b0 + g * 4 + i], ~key);
            }
        }
    }

    // ---- last-block epilogue: write bmus, re-arm globals for next replay ----
    __shared__ unsigned int s_last;
    __syncthreads();
    if (threadIdx.x == 0) {
        __threadfence();  // make this block's g_best updates globally visible
        unsigned int ticket = atomicAdd(&g_done, 1);
        s_last = (ticket == NBLOCKS - 1) ? 1u : 0u;
    }
    __syncthreads();
    if (s_last) {
        __threadfence();  // acquire: see all other blocks' g_best updates
        if (threadIdx.x < B) {
            unsigned long long v = ~g_best[threadIdx.x];
            unsigned int mm = (unsigned int)(v & 0xFFFFFFFFu);
            out[threadIdx.x * 2 + 0] = (float)(mm >> 6);   // row
            out[threadIdx.x * 2 + 1] = (float)(mm & 63);   // col
            g_best[threadIdx.x] = 0ULL;                    // re-arm
        }
        if (threadIdx.x == 0) g_done = 0;                  // re-arm ticket
    }
}

extern "C" void kernel_launch(void* const* d_in, const int* in_sizes, int n_in,
                              void* d_out, int out_size) {
    const float* x = (const float*)d_in[0];
    const float* w = (const float*)d_in[1];
    som_fused_kernel<<<NBLOCKS, 256>>>(x, w, (float*)d_out);
}

// round 4
// speedup vs baseline: 1.6743x; 1.0012x over previous
#include <cuda_runtime.h>
#include <cstdint>

// SOM forward: x[128,256] f32, weights[64,64,256] f32
// out = [ bmus(128*2 floats) , diffs(128*64*64*256 floats) ]
//
// R4: latency-bound fix. Streaming loop has NO cross-lane ops: per-lane
// partial d2 accumulators acc[8], software-pipelined x loads, coalesced
// __stcs stores. All shuffle reductions + atomics deferred to after the
// loop (8 independent chains). Single launch, last-block epilogue writes
// bmus and re-arms globals (graph-replay deterministic).

#define B 128
#define D 256
#define MAPM 4096            // 64*64 neurons
#define CHUNK 8              // batches per warp
#define NCHUNK (B / CHUNK)   // 16 chunks per neuron
#define WARPS_PER_BLOCK 8
#define NBLOCKS (MAPM * NCHUNK / WARPS_PER_BLOCK)  // 8192

__device__ unsigned long long g_best[B];   // zero-init; holds ~min_key
__device__ unsigned int g_done;            // zero-init ticket

__global__ __launch_bounds__(256) void som_fused_kernel(
    const float* __restrict__ x,
    const float* __restrict__ w,
    float* __restrict__ out)   // out = [bmus | diffs]
{
    float* __restrict__ diffs = out + B * 2;

    const int gwarp = blockIdx.x * WARPS_PER_BLOCK + (threadIdx.x >> 5);
    const int lane  = threadIdx.x & 31;
    const int m     = gwarp >> 4;              // 0..4095  (16 chunks per m)
    const int b0    = (gwarp & 15) * CHUNK;    // chunk start batch

    // weight row in registers (contiguous 512B per LDG.128)
    const float4* __restrict__ wv = reinterpret_cast<const float4*>(w + (size_t)m * D);
    const float4 wa0 = wv[lane];
    const float4 wa1 = wv[32 + lane];

    float acc[CHUNK];

    // software-pipelined prefetch of x
    const float4* __restrict__ xv0 =
        reinterpret_cast<const float4*>(x + (size_t)b0 * D);
    float4 xn0 = xv0[lane];
    float4 xn1 = xv0[32 + lane];

    float4* __restrict__ ov =
        reinterpret_cast<float4*>(diffs + ((size_t)b0 * MAPM + m) * D);

#pragma unroll
    for (int i = 0; i < CHUNK; i++) {
        float4 xa0 = xn0;
        float4 xa1 = xn1;
        if (i + 1 < CHUNK) {
            const float4* __restrict__ xv =
                reinterpret_cast<const float4*>(x + (size_t)(b0 + i + 1) * D);
            xn0 = xv[lane];          // prefetch next batch, independent
            xn1 = xv[32 + lane];
        }

        float4 d0, d1;
        d0.x = xa0.x - wa0.x;  d0.y = xa0.y - wa0.y;
        d0.z = xa0.z - wa0.z;  d0.w = xa0.w - wa0.w;
        d1.x = xa1.x - wa1.x;  d1.y = xa1.y - wa1.y;
        d1.z = xa1.z - wa1.z;  d1.w = xa1.w - wa1.w;

        __stcs(ov + lane,      d0);   // streaming store, evict-first
        __stcs(ov + 32 + lane, d1);
        ov += MAPM * D / 4;           // next b, same m

        float a;
        a = d0.x * d0.x;
        a = fmaf(d0.y, d0.y, a);
        a = fmaf(d0.z, d0.z, a);
        a = fmaf(d0.w, d0.w, a);
        a = fmaf(d1.x, d1.x, a);
        a = fmaf(d1.y, d1.y, a);
        a = fmaf(d1.z, d1.z, a);
        a = fmaf(d1.w, d1.w, a);
        acc[i] = a;                   // per-lane partial; NO cross-lane ops here
    }

    // 8 independent warp reductions, interleaved (latency overlapped)
#pragma unroll
    for (int off = 16; off; off >>= 1) {
#pragma unroll
        for (int i = 0; i < CHUNK; i++)
            acc[i] += __shfl_down_sync(0xffffffffu, acc[i], off);
    }

    if (lane == 0) {
        const unsigned int mbits = (unsigned int)m;
#pragma unroll
        for (int i = 0; i < CHUNK; i++) {
            // min over key == max over ~key (zero-init safe). Low bits carry
            // m -> ties resolve to lowest index (argmin semantics).
            unsigned long long key =
                ((unsigned long long)__float_as_uint(acc[i]) << 32) | mbits;
            atomicMax(&g_best[b0 + i], ~key);
        }
    }

    // ---- last-block epilogue: write bmus, re-arm globals for next replay ----
    __shared__ unsigned int s_last;
    __syncthreads();
    if (threadIdx.x == 0) {
        __threadfence();  // publish this block's g_best updates
        unsigned int ticket = atomicAdd(&g_done, 1);
        s_last = (ticket == NBLOCKS - 1) ? 1u : 0u;
    }
    __syncthreads();
    if (s_last) {
        __threadfence();  // acquire all other blocks' g_best updates
        if (threadIdx.x < B) {
            unsigned long long v = ~g_best[threadIdx.x];
            unsigned int mm = (unsigned int)(v & 0xFFFFFFFFu);
            out[threadIdx.x * 2 + 0] = (float)(mm >> 6);   // row
            out[threadIdx.x * 2 + 1] = (float)(mm & 63);   // col
            g_best[threadIdx.x] = 0ULL;                    // re-arm
        }
        if (threadIdx.x == 0) g_done = 0;                  // re-arm ticket
    }
}

extern "C" void kernel_launch(void* const* d_in, const int* in_sizes, int n_in,
                              void* d_out, int out_size) {
    const float* x = (const float*)d_in[0];
    const float* w = (const float*)d_in[1];
    som_fused_kernel<<<NBLOCKS, 256>>>(x, w, (float*)d_out);
}

// round 5
// speedup vs baseline: 4.4214x; 2.6407x over previous
#include <cuda_runtime.h>
#include <cstdint>

// SOM forward: x[128,256] f32, weights[64,64,256] f32
// out = [ bmus(128*2 floats) , diffs(128*64*64*256 floats) ]
//
// R5: DRAM-locality fix. Warp = (batch b, 16 CONTIGUOUS neurons) -> each
// warp writes one contiguous 16KB stream (block: 128KB), reads contiguous
// w slab (L2-resident, 4MB). x[b] in registers. Per-lane acc[16], deferred
// interleaved reductions, ONE atomic per warp. Single launch; last-block
// epilogue writes bmus and re-arms globals (graph-replay deterministic).

#define B 128
#define D 256
#define MAPM 4096                 // 64*64 neurons
#define M_PER_WARP 16
#define WARPS_PER_BLOCK 8
#define M_PER_BLOCK (M_PER_WARP * WARPS_PER_BLOCK)  // 128
#define MBLOCKS (MAPM / M_PER_BLOCK)                // 32
#define NBLOCKS (B * MBLOCKS)                       // 4096

__device__ unsigned long long g_best[B];   // zero-init; holds ~min_key
__device__ unsigned int g_done;            // zero-init ticket

__global__ __launch_bounds__(256) void som_fused_kernel(
    const float* __restrict__ x,
    const float* __restrict__ w,
    float* __restrict__ out)   // out = [bmus | diffs]
{
    float* __restrict__ diffs = out + B * 2;

    const int warp = threadIdx.x >> 5;
    const int lane = threadIdx.x & 31;
    const int b    = blockIdx.x >> 5;                       // 0..127
    const int mb   = blockIdx.x & 31;                       // 0..31
    const int m0   = mb * M_PER_BLOCK + warp * M_PER_WARP;  // warp's first m

    // x[b] in registers (shared by all 16 neurons)
    const float4* __restrict__ xv = reinterpret_cast<const float4*>(x + (size_t)b * D);
    const float4 xa0 = xv[lane];
    const float4 xa1 = xv[32 + lane];

    const float4* __restrict__ wv =
        reinterpret_cast<const float4*>(w + (size_t)m0 * D);
    float4* __restrict__ ov =
        reinterpret_cast<float4*>(diffs + ((size_t)b * MAPM + m0) * D);

    float acc[M_PER_WARP];

    // 1-deep software pipeline on the w row
    float4 wn0 = wv[lane];
    float4 wn1 = wv[32 + lane];

#pragma unroll
    for (int i = 0; i < M_PER_WARP; i++) {
        float4 wa0 = wn0, wa1 = wn1;
        if (i + 1 < M_PER_WARP) {
            wn0 = wv[(i + 1) * 64 + lane];        // contiguous next w row
            wn1 = wv[(i + 1) * 64 + 32 + lane];
        }

        float4 d0, d1;
        d0.x = xa0.x - wa0.x;  d0.y = xa0.y - wa0.y;
        d0.z = xa0.z - wa0.z;  d0.w = xa0.w - wa0.w;
        d1.x = xa1.x - wa1.x;  d1.y = xa1.y - wa1.y;
        d1.z = xa1.z - wa1.z;  d1.w = xa1.w - wa1.w;

        // contiguous streaming stores: warp covers [m0*1KB, m0*1KB + 16KB)
        __stcs(ov + i * 64 + lane,      d0);
        __stcs(ov + i * 64 + 32 + lane, d1);

        float a;
        a = d0.x * d0.x;
        a = fmaf(d0.y, d0.y, a);
        a = fmaf(d0.z, d0.z, a);
        a = fmaf(d0.w, d0.w, a);
        a = fmaf(d1.x, d1.x, a);
        a = fmaf(d1.y, d1.y, a);
        a = fmaf(d1.z, d1.z, a);
        a = fmaf(d1.w, d1.w, a);
        acc[i] = a;                    // per-lane partial; no cross-lane ops
    }

    // 16 independent warp reductions, interleaved (latency overlapped)
#pragma unroll
    for (int off = 16; off; off >>= 1) {
#pragma unroll
        for (int i = 0; i < M_PER_WARP; i++)
            acc[i] += __shfl_down_sync(0xffffffffu, acc[i], off);
    }

    if (lane == 0) {
        // local argmin over this warp's 16 neurons, then ONE global atomic.
        // key = (d2_bits << 32) | m: u64 min == argmin with lowest-m ties.
        unsigned long long best = 0xFFFFFFFFFFFFFFFFULL;
#pragma unroll
        for (int i = 0; i < M_PER_WARP; i++) {
            unsigned long long key =
                ((unsigned long long)__float_as_uint(acc[i]) << 32) |
                (unsigned int)(m0 + i);
            best = (key < best) ? key : best;
        }
        atomicMax(&g_best[b], ~best);   // min(key) == max(~key); zero-init safe
    }

    // ---- last-block epilogue: write bmus, re-arm globals for next replay ----
    __shared__ unsigned int s_last;
    __syncthreads();
    if (threadIdx.x == 0) {
        __threadfence();  // publish this block's g_best update
        unsigned int ticket = atomicAdd(&g_done, 1);
        s_last = (ticket == NBLOCKS - 1) ? 1u : 0u;
    }
    __syncthreads();
    if (s_last) {
        __threadfence();  // acquire all other blocks' g_best updates
        if (threadIdx.x < B) {
            unsigned long long v = ~g_best[threadIdx.x];
            unsigned int mm = (unsigned int)(v & 0xFFFFFFFFu);
            out[threadIdx.x * 2 + 0] = (float)(mm >> 6);   // row
            out[threadIdx.x * 2 + 1] = (float)(mm & 63);   // col
            g_best[threadIdx.x] = 0ULL;                    // re-arm
        }
        if (threadIdx.x == 0) g_done = 0;                  // re-arm ticket
    }
}

extern "C" void kernel_launch(void* const* d_in, const int* in_sizes, int n_in,
                              void* d_out, int out_size) {
    const float* x = (const float*)d_in[0];
    const float* w = (const float*)d_in[1];
    som_fused_kernel<<<NBLOCKS, 256>>>(x, w, (float*)d_out);
}